// round 6
// baseline (speedup 1.0000x reference)
#include <cuda_runtime.h>
#include <cuda_fp16.h>
#include <cstdint>

// Problem constants
#define Bn 131072
#define Cn 128
#define En 128
#define TM 128              // samples per block
#define NBLK (Bn / TM)      // 1024 blocks
#define PADH 136            // smem row stride in halves (272B) -> conflict-free frags

// ArcFace constants (m = 1.0, s = 100)
#define COSM 0.5403023058681398f
#define SINM 0.8414709848078965f
#define THv  (-0.5403023058681398f)
#define MMv  0.8414709848078965f
#define Sv   100.0f
#define SHIFT 30.0f         // fixed logit shift: exp(z-30) never overflows (z<=100.1)

// Scratch (no allocation allowed -> device globals)
__device__ __half g_wn16[Cn * En];   // normalized weight fp16, row-major [C][E]
__device__ float  g_bsum[NBLK];
__device__ int    g_cnt;             // zero-init; reset by last block each launch

// smem byte offsets
#define OFF_A    0                   // half[128][136] = 34816 B
#define OFF_B    34816               // half[128][136] = 34816 B
#define OFF_RED  69632               // float[8]
#define OFF_FLAG 69664               // int
#define SMEM_SZ  69696

__device__ __forceinline__ void hmma16816(float& c0, float& c1, float& c2, float& c3,
                                          uint32_t a0, uint32_t a1, uint32_t a2, uint32_t a3,
                                          uint32_t b0, uint32_t b1) {
    asm volatile(
        "mma.sync.aligned.m16n8k16.row.col.f32.f16.f16.f32 "
        "{%0,%1,%2,%3}, {%4,%5,%6,%7}, {%8,%9}, {%0,%1,%2,%3};"
        : "+f"(c0), "+f"(c1), "+f"(c2), "+f"(c3)
        : "r"(a0), "r"(a1), "r"(a2), "r"(a3), "r"(b0), "r"(b1));
}

// ---------------------------------------------------------------------------
// prep: normalize weight rows -> fp16 row-major global. 16 blocks x 256 thr.
// ---------------------------------------------------------------------------
__global__ void prep_kernel(const float* __restrict__ weight)
{
    const int lane = threadIdx.x & 31;
    const int w    = threadIdx.x >> 5;
    const int row  = blockIdx.x * 8 + w;

    float4 v = reinterpret_cast<const float4*>(weight)[row * 32 + lane];
    float ss = v.x * v.x + v.y * v.y + v.z * v.z + v.w * v.w;
    #pragma unroll
    for (int o = 16; o; o >>= 1) ss += __shfl_xor_sync(0xffffffffu, ss, o);
    float r = 1.0f / fmaxf(sqrtf(ss), 1e-12f);

    __half2 h0 = __floats2half2_rn(v.x * r, v.y * r);
    __half2 h1 = __floats2half2_rn(v.z * r, v.w * r);
    unsigned long long pk;
    asm("mov.b64 %0,{%1,%2};" : "=l"(pk)
        : "r"(*(uint32_t*)&h0), "r"(*(uint32_t*)&h1));
    *reinterpret_cast<unsigned long long*>(
        reinterpret_cast<char*>(g_wn16) + row * 256 + lane * 8) = pk;
}

// NLL from label-EXCLUDED shifted sum se = sum exp(z-30), and label cosine cs.
__device__ __forceinline__ float row_nll(float se, float cs) {
    float sn  = sqrtf(fmaxf(1.0f - cs * cs, 0.0f));
    float phi = (cs > THv) ? (cs * COSM - sn * SINM) : (cs - MMv);
    float zl  = Sv * phi;
    float se2 = se + __expf(zl - SHIFT);
    return (SHIFT + __logf(se2)) - zl;
}

// ---------------------------------------------------------------------------
// main kernel: 3 CTAs/SM (85-reg cap), single-pass fixed-shift epilogue
// ---------------------------------------------------------------------------
__global__ void __launch_bounds__(256, 3)
arc_main(const float* __restrict__ predict,
         const float* __restrict__ target,
         float* __restrict__ out)
{
    extern __shared__ char sm[];
    char*  sA   = sm + OFF_A;
    char*  sB   = sm + OFF_B;
    float* red  = (float*)(sm + OFF_RED);
    int*   flag = (int*)(sm + OFF_FLAG);

    const int tid  = threadIdx.x;
    const int lane = tid & 31;
    const int w    = tid >> 5;
    const int blk  = blockIdx.x;
    const int g    = lane >> 2;      // fragment row group 0..7
    const int c    = lane & 3;       // fragment col group 0..3

    // ---- B tile: copy normalized fp16 weights into padded smem (uint4) ----
    {
        const uint4* gw = (const uint4*)g_wn16;   // 2048 uint4
        #pragma unroll
        for (int i = 0; i < 8; i++) {
            int idx = i * 256 + tid;              // uint4 index; 16 per row
            *(uint4*)(sB + (idx >> 4) * (PADH * 2) + (idx & 15) * 16) = gw[idx];
        }
    }

    // ---- A tile: raw fp16 store (no pre-normalization); per-row partials ----
    float ssq[16];    // per-lane partial sum-of-squares for warp-local rows
    float lix[16];    // per-lane partial label index (exact, one-hot dot iota)
    const float i0 = (float)(lane * 4), i1 = i0 + 1.0f, i2 = i0 + 2.0f, i3 = i0 + 3.0f;

    #pragma unroll 4
    for (int it = 0; it < 16; it++) {
        const int row = w * 16 + it;
        const size_t gidx = (size_t)(blk * TM + row) * 32 + lane;
        float4 v = reinterpret_cast<const float4*>(predict)[gidx];
        float4 t = reinterpret_cast<const float4*>(target)[gidx];

        __half2 h0 = __floats2half2_rn(v.x, v.y);
        __half2 h1 = __floats2half2_rn(v.z, v.w);
        unsigned long long pk;
        asm("mov.b64 %0,{%1,%2};" : "=l"(pk)
            : "r"(*(uint32_t*)&h0), "r"(*(uint32_t*)&h1));
        *reinterpret_cast<unsigned long long*>(sA + row * (PADH * 2) + lane * 8) = pk;

        ssq[it] = fmaf(v.x, v.x, fmaf(v.y, v.y, fmaf(v.z, v.z, v.w * v.w)));
        lix[it] = fmaf(t.x, i0, fmaf(t.y, i1, fmaf(t.z, i2, t.w * i3)));
    }

    // ---- one vectorized butterfly: 16 row-sums (norm^2) + 16 labels ----
    #pragma unroll
    for (int o = 16; o; o >>= 1) {
        #pragma unroll
        for (int i = 0; i < 16; i++) {
            ssq[i] += __shfl_xor_sync(0xffffffffu, ssq[i], o);
            lix[i] += __shfl_xor_sync(0xffffffffu, lix[i], o);
        }
    }
    float ss0 = 0.f, ss1 = 0.f, lf0 = 0.f, lf1 = 0.f;
    #pragma unroll
    for (int i = 0; i < 8; i++) {
        if (i == g) { ss0 = ssq[i]; lf0 = lix[i]; ss1 = ssq[i + 8]; lf1 = lix[i + 8]; }
    }
    const float invn0 = rsqrtf(fmaxf(ss0, 1e-24f));
    const float invn1 = rsqrtf(fmaxf(ss1, 1e-24f));
    const int   lbl0  = (int)lf0;
    const int   lbl1  = (int)lf1;

    __syncthreads();

    // ---- A fragments (reused across all 16 tiles) ----
    const int r0 = w * 16 + g;
    uint32_t A0[8], A1[8], A2[8], A3[8];
    {
        const char* a_lo = sA + r0 * (PADH * 2) + c * 4;
        const char* a_hi = a_lo + 8 * (PADH * 2);
        #pragma unroll
        for (int ks = 0; ks < 8; ks++) {
            A0[ks] = *(const uint32_t*)(a_lo + ks * 32);
            A2[ks] = *(const uint32_t*)(a_lo + ks * 32 + 16);
            A1[ks] = *(const uint32_t*)(a_hi + ks * 32);
            A3[ks] = *(const uint32_t*)(a_hi + ks * 32 + 16);
        }
    }

    // ---- single-pass: HMMA tile -> fixed-shift exps -> accumulate ----
    const float sI0 = Sv * invn0, sI1 = Sv * invn1;
    float ac00 = 0.f, ac01 = 0.f, ac10 = 0.f, ac11 = 0.f;
    float cs0 = -2.0f, cs1 = -2.0f;

    #pragma unroll
    for (int t = 0; t < 16; t++) {
        float c0 = 0.f, c1 = 0.f, c2 = 0.f, c3 = 0.f;
        const char* bb = sB + (8 * t + g) * (PADH * 2) + c * 4;
        #pragma unroll
        for (int ks = 0; ks < 8; ks++) {
            uint32_t b0 = *(const uint32_t*)(bb + ks * 32);
            uint32_t b1 = *(const uint32_t*)(bb + ks * 32 + 16);
            hmma16816(c0, c1, c2, c3, A0[ks], A1[ks], A2[ks], A3[ks], b0, b1);
        }
        const int n0 = 8 * t + 2 * c;   // this lane's cols in tile t

        float e0 = __expf(fmaf(c0, sI0, -SHIFT));
        float e1 = __expf(fmaf(c1, sI0, -SHIFT));
        float e2 = __expf(fmaf(c2, sI1, -SHIFT));
        float e3 = __expf(fmaf(c3, sI1, -SHIFT));
        if (n0     == lbl0) { cs0 = c0 * invn0; e0 = 0.f; }
        if (n0 + 1 == lbl0) { cs0 = c1 * invn0; e1 = 0.f; }
        if (n0     == lbl1) { cs1 = c2 * invn1; e2 = 0.f; }
        if (n0 + 1 == lbl1) { cs1 = c3 * invn1; e3 = 0.f; }
        ac00 += e0; ac01 += e1; ac10 += e2; ac11 += e3;
    }

    float se0 = ac00 + ac01;
    float se1 = ac10 + ac11;
    se0 += __shfl_xor_sync(0xffffffffu, se0, 1);
    se0 += __shfl_xor_sync(0xffffffffu, se0, 2);
    se1 += __shfl_xor_sync(0xffffffffu, se1, 1);
    se1 += __shfl_xor_sync(0xffffffffu, se1, 2);
    cs0 = fmaxf(cs0, __shfl_xor_sync(0xffffffffu, cs0, 1));
    cs0 = fmaxf(cs0, __shfl_xor_sync(0xffffffffu, cs0, 2));
    cs1 = fmaxf(cs1, __shfl_xor_sync(0xffffffffu, cs1, 1));
    cs1 = fmaxf(cs1, __shfl_xor_sync(0xffffffffu, cs1, 2));

    // per-row NLL (lane c==0 contributes) then warp sum
    float nll = row_nll(se0, cs0) + row_nll(se1, cs1);
    if (c != 0) nll = 0.0f;
    #pragma unroll
    for (int o = 16; o; o >>= 1) nll += __shfl_xor_sync(0xffffffffu, nll, o);
    if (lane == 0) red[w] = nll;
    __syncthreads();

    if (tid == 0) {
        float t = 0.0f;
        #pragma unroll
        for (int i = 0; i < 8; i++) t += red[i];
        g_bsum[blk] = t;
        __threadfence();
        int cdone = atomicAdd(&g_cnt, 1);
        *flag = (cdone == NBLK - 1) ? 1 : 0;
    }
    __syncthreads();

    // last block: deterministic final reduction -> mean
    if (*flag) {
        __threadfence();
        float t = g_bsum[tid] + g_bsum[tid + 256] + g_bsum[tid + 512] + g_bsum[tid + 768];
        float* fr = (float*)(sm + OFF_A);   // reuse smem
        fr[tid] = t;
        __syncthreads();
        #pragma unroll
        for (int st = 128; st; st >>= 1) {
            if (tid < st) fr[tid] += fr[tid + st];
            __syncthreads();
        }
        if (tid == 0) {
            out[0] = fr[0] / (float)Bn;
            g_cnt  = 0;
        }
    }
}

// ---------------------------------------------------------------------------
extern "C" void kernel_launch(void* const* d_in, const int* in_sizes, int n_in,
                              void* d_out, int out_size)
{
    (void)in_sizes; (void)n_in; (void)out_size;
    const float* predict = (const float*)d_in[0];
    const float* target  = (const float*)d_in[1];
    const float* weight  = (const float*)d_in[2];

    cudaFuncSetAttribute(arc_main, cudaFuncAttributeMaxDynamicSharedMemorySize, SMEM_SZ);

    prep_kernel<<<16, 256>>>(weight);
    arc_main<<<NBLK, 256, SMEM_SZ>>>(predict, target, (float*)d_out);
}

// round 7
// speedup vs baseline: 1.0530x; 1.0530x over previous
#include <cuda_runtime.h>
#include <cuda_fp16.h>
#include <cstdint>

// Problem constants
#define Bn 131072
#define Cn 128
#define En 128
#define TM 128              // samples per block
#define NBLK (Bn / TM)      // 1024 blocks
#define PADH 136            // smem row stride in halves (272B) -> conflict-free frags

// ArcFace constants (m = 1.0, s = 100)
#define COSM 0.5403023058681398f
#define SINM 0.8414709848078965f
#define THv  (-0.5403023058681398f)
#define MMv  0.8414709848078965f
#define Sv   100.0f
#define SHIFT 30.0f         // fixed logit shift: exp(z-30) never overflows (z<=100.1)

// Scratch (no allocation allowed -> device globals)
__device__ __half g_wn16[Cn * En];   // normalized weight fp16, row-major [C][E]
__device__ float  g_bsum[NBLK];
__device__ int    g_cnt;             // zero-init; reset by last block each launch

// smem byte offsets
#define OFF_A    0                   // half[128][136] = 34816 B
#define OFF_B    34816               // half[128][136] = 34816 B
#define OFF_RED  69632               // float[8]
#define OFF_FLAG 69664               // int
#define SMEM_SZ  69696

__device__ __forceinline__ void hmma16816(float& c0, float& c1, float& c2, float& c3,
                                          uint32_t a0, uint32_t a1, uint32_t a2, uint32_t a3,
                                          uint32_t b0, uint32_t b1) {
    asm volatile(
        "mma.sync.aligned.m16n8k16.row.col.f32.f16.f16.f32 "
        "{%0,%1,%2,%3}, {%4,%5,%6,%7}, {%8,%9}, {%0,%1,%2,%3};"
        : "+f"(c0), "+f"(c1), "+f"(c2), "+f"(c3)
        : "r"(a0), "r"(a1), "r"(a2), "r"(a3), "r"(b0), "r"(b1));
}

// ---------------------------------------------------------------------------
// prep: normalize weight rows -> fp16 row-major global. 16 blocks x 256 thr.
// ---------------------------------------------------------------------------
__global__ void prep_kernel(const float* __restrict__ weight)
{
    const int lane = threadIdx.x & 31;
    const int w    = threadIdx.x >> 5;
    const int row  = blockIdx.x * 8 + w;

    float4 v = reinterpret_cast<const float4*>(weight)[row * 32 + lane];
    float ss = v.x * v.x + v.y * v.y + v.z * v.z + v.w * v.w;
    #pragma unroll
    for (int o = 16; o; o >>= 1) ss += __shfl_xor_sync(0xffffffffu, ss, o);
    float r = 1.0f / fmaxf(sqrtf(ss), 1e-12f);

    __half2 h0 = __floats2half2_rn(v.x * r, v.y * r);
    __half2 h1 = __floats2half2_rn(v.z * r, v.w * r);
    unsigned long long pk;
    asm("mov.b64 %0,{%1,%2};" : "=l"(pk)
        : "r"(*(uint32_t*)&h0), "r"(*(uint32_t*)&h1));
    *reinterpret_cast<unsigned long long*>(
        reinterpret_cast<char*>(g_wn16) + row * 256 + lane * 8) = pk;
}

// NLL from label-EXCLUDED shifted sum se = sum exp(z-30), and label cosine cs.
__device__ __forceinline__ float row_nll(float se, float cs) {
    float sn  = sqrtf(fmaxf(1.0f - cs * cs, 0.0f));
    float phi = (cs > THv) ? (cs * COSM - sn * SINM) : (cs - MMv);
    float zl  = Sv * phi;
    float se2 = se + __expf(zl - SHIFT);
    return (SHIFT + __logf(se2)) - zl;
}

// ---------------------------------------------------------------------------
// main kernel: 2 CTAs/SM, dual-accumulator HMMA, warp-private A path
// ---------------------------------------------------------------------------
__global__ void __launch_bounds__(256, 2)
arc_main(const float* __restrict__ predict,
         const float* __restrict__ target,
         float* __restrict__ out)
{
    extern __shared__ char sm[];
    char*  sA   = sm + OFF_A;
    char*  sB   = sm + OFF_B;
    float* red  = (float*)(sm + OFF_RED);
    int*   flag = (int*)(sm + OFF_FLAG);

    const int tid  = threadIdx.x;
    const int lane = tid & 31;
    const int w    = tid >> 5;
    const int blk  = blockIdx.x;
    const int g    = lane >> 2;      // fragment row group 0..7
    const int c    = lane & 3;       // fragment col group 0..3

    // ---- B tile first (block-shared), sync immediately ----
    {
        const uint4* gw = (const uint4*)g_wn16;   // 2048 uint4
        #pragma unroll
        for (int i = 0; i < 8; i++) {
            int idx = i * 256 + tid;              // uint4 index; 16 per row
            *(uint4*)(sB + (idx >> 4) * (PADH * 2) + (idx & 15) * 16) = gw[idx];
        }
    }
    __syncthreads();

    // ---- A tile: raw fp16 store (warp-private rows); per-row partials ----
    float ssq[16];    // per-lane partial sum-of-squares for warp-local rows
    float lix[16];    // per-lane partial label index (exact, one-hot dot iota)
    const float i0 = (float)(lane * 4), i1 = i0 + 1.0f, i2 = i0 + 2.0f, i3 = i0 + 3.0f;

    #pragma unroll 8
    for (int it = 0; it < 16; it++) {
        const int row = w * 16 + it;
        const size_t gidx = (size_t)(blk * TM + row) * 32 + lane;
        float4 v = reinterpret_cast<const float4*>(predict)[gidx];
        float4 t = reinterpret_cast<const float4*>(target)[gidx];

        __half2 h0 = __floats2half2_rn(v.x, v.y);
        __half2 h1 = __floats2half2_rn(v.z, v.w);
        unsigned long long pk;
        asm("mov.b64 %0,{%1,%2};" : "=l"(pk)
            : "r"(*(uint32_t*)&h0), "r"(*(uint32_t*)&h1));
        *reinterpret_cast<unsigned long long*>(sA + row * (PADH * 2) + lane * 8) = pk;

        ssq[it] = fmaf(v.x, v.x, fmaf(v.y, v.y, fmaf(v.z, v.z, v.w * v.w)));
        lix[it] = fmaf(t.x, i0, fmaf(t.y, i1, fmaf(t.z, i2, t.w * i3)));
    }

    // ---- one vectorized butterfly: 16 row-sums (norm^2) + 16 labels ----
    #pragma unroll
    for (int o = 16; o; o >>= 1) {
        #pragma unroll
        for (int i = 0; i < 16; i++) {
            ssq[i] += __shfl_xor_sync(0xffffffffu, ssq[i], o);
            lix[i] += __shfl_xor_sync(0xffffffffu, lix[i], o);
        }
    }
    float ss0 = 0.f, ss1 = 0.f, lf0 = 0.f, lf1 = 0.f;
    #pragma unroll
    for (int i = 0; i < 8; i++) {
        if (i == g) { ss0 = ssq[i]; lf0 = lix[i]; ss1 = ssq[i + 8]; lf1 = lix[i + 8]; }
    }
    const float invn0 = rsqrtf(fmaxf(ss0, 1e-24f));
    const float invn1 = rsqrtf(fmaxf(ss1, 1e-24f));
    const int   lbl0  = (int)lf0;
    const int   lbl1  = (int)lf1;

    __syncwarp();   // A rows are warp-private: warp-level visibility suffices

    // ---- A fragments (reused across all 16 tiles) ----
    const int r0 = w * 16 + g;
    uint32_t A0[8], A1[8], A2[8], A3[8];
    {
        const char* a_lo = sA + r0 * (PADH * 2) + c * 4;
        const char* a_hi = a_lo + 8 * (PADH * 2);
        #pragma unroll
        for (int ks = 0; ks < 8; ks++) {
            A0[ks] = *(const uint32_t*)(a_lo + ks * 32);
            A2[ks] = *(const uint32_t*)(a_lo + ks * 32 + 16);
            A1[ks] = *(const uint32_t*)(a_hi + ks * 32);
            A3[ks] = *(const uint32_t*)(a_hi + ks * 32 + 16);
        }
    }

    // ---- single-pass: dual-accumulator HMMA -> fixed-shift exps ----
    const float sI0 = Sv * invn0, sI1 = Sv * invn1;
    float ac00 = 0.f, ac01 = 0.f, ac10 = 0.f, ac11 = 0.f;
    float cs0 = -2.0f, cs1 = -2.0f;

    #pragma unroll
    for (int t = 0; t < 16; t++) {
        // two independent accumulator sets (even/odd k-steps) -> 2x HMMA ILP
        float x0 = 0.f, x1 = 0.f, x2 = 0.f, x3 = 0.f;
        float y0 = 0.f, y1 = 0.f, y2 = 0.f, y3 = 0.f;
        const char* bb = sB + (8 * t + g) * (PADH * 2) + c * 4;
        #pragma unroll
        for (int ks = 0; ks < 8; ks += 2) {
            uint32_t b0 = *(const uint32_t*)(bb + ks * 32);
            uint32_t b1 = *(const uint32_t*)(bb + ks * 32 + 16);
            hmma16816(x0, x1, x2, x3, A0[ks], A1[ks], A2[ks], A3[ks], b0, b1);
            uint32_t b2 = *(const uint32_t*)(bb + ks * 32 + 32);
            uint32_t b3 = *(const uint32_t*)(bb + ks * 32 + 48);
            hmma16816(y0, y1, y2, y3, A0[ks + 1], A1[ks + 1], A2[ks + 1], A3[ks + 1], b2, b3);
        }
        const float c0 = x0 + y0, c1 = x1 + y1, c2 = x2 + y2, c3 = x3 + y3;
        const int n0 = 8 * t + 2 * c;   // this lane's cols in tile t

        float e0 = __expf(fmaf(c0, sI0, -SHIFT));
        float e1 = __expf(fmaf(c1, sI0, -SHIFT));
        float e2 = __expf(fmaf(c2, sI1, -SHIFT));
        float e3 = __expf(fmaf(c3, sI1, -SHIFT));
        if (n0     == lbl0) { cs0 = c0 * invn0; e0 = 0.f; }
        if (n0 + 1 == lbl0) { cs0 = c1 * invn0; e1 = 0.f; }
        if (n0     == lbl1) { cs1 = c2 * invn1; e2 = 0.f; }
        if (n0 + 1 == lbl1) { cs1 = c3 * invn1; e3 = 0.f; }
        ac00 += e0; ac01 += e1; ac10 += e2; ac11 += e3;
    }

    float se0 = ac00 + ac01;
    float se1 = ac10 + ac11;
    se0 += __shfl_xor_sync(0xffffffffu, se0, 1);
    se0 += __shfl_xor_sync(0xffffffffu, se0, 2);
    se1 += __shfl_xor_sync(0xffffffffu, se1, 1);
    se1 += __shfl_xor_sync(0xffffffffu, se1, 2);
    cs0 = fmaxf(cs0, __shfl_xor_sync(0xffffffffu, cs0, 1));
    cs0 = fmaxf(cs0, __shfl_xor_sync(0xffffffffu, cs0, 2));
    cs1 = fmaxf(cs1, __shfl_xor_sync(0xffffffffu, cs1, 1));
    cs1 = fmaxf(cs1, __shfl_xor_sync(0xffffffffu, cs1, 2));

    // per-row NLL (lane c==0 contributes) then warp sum
    float nll = row_nll(se0, cs0) + row_nll(se1, cs1);
    if (c != 0) nll = 0.0f;
    #pragma unroll
    for (int o = 16; o; o >>= 1) nll += __shfl_xor_sync(0xffffffffu, nll, o);
    if (lane == 0) red[w] = nll;
    __syncthreads();

    if (tid == 0) {
        float t = 0.0f;
        #pragma unroll
        for (int i = 0; i < 8; i++) t += red[i];
        g_bsum[blk] = t;
        __threadfence();
        int cdone = atomicAdd(&g_cnt, 1);
        *flag = (cdone == NBLK - 1) ? 1 : 0;
    }
    __syncthreads();

    // last block: deterministic final reduction -> mean
    if (*flag) {
        __threadfence();
        float t = g_bsum[tid] + g_bsum[tid + 256] + g_bsum[tid + 512] + g_bsum[tid + 768];
        float* fr = (float*)(sm + OFF_A);   // reuse smem
        fr[tid] = t;
        __syncthreads();
        #pragma unroll
        for (int st = 128; st; st >>= 1) {
            if (tid < st) fr[tid] += fr[tid + st];
            __syncthreads();
        }
        if (tid == 0) {
            out[0] = fr[0] / (float)Bn;
            g_cnt  = 0;
        }
    }
}

// ---------------------------------------------------------------------------
extern "C" void kernel_launch(void* const* d_in, const int* in_sizes, int n_in,
                              void* d_out, int out_size)
{
    (void)in_sizes; (void)n_in; (void)out_size;
    const float* predict = (const float*)d_in[0];
    const float* target  = (const float*)d_in[1];
    const float* weight  = (const float*)d_in[2];

    cudaFuncSetAttribute(arc_main, cudaFuncAttributeMaxDynamicSharedMemorySize, SMEM_SZ);

    prep_kernel<<<16, 256>>>(weight);
    arc_main<<<NBLK, 256, SMEM_SZ>>>(predict, target, (float*)d_out);
}

// round 8
// speedup vs baseline: 1.3802x; 1.3107x over previous
#include <cuda_runtime.h>
#include <cuda_fp16.h>
#include <cstdint>

// Problem constants
#define Bn 131072
#define Cn 128
#define En 128
#define TM 128              // samples per tile
#define NTILES (Bn / TM)    // 1024
#define NPERS 296           // persistent CTAs (2 per SM on 148 SMs)

// ArcFace constants (m = 1.0, s = 100)
#define COSM 0.5403023058681398f
#define SINM 0.8414709848078965f
#define THv  (-0.5403023058681398f)
#define MMv  0.8414709848078965f
#define Sv   100.0f
#define SHIFT 30.0f         // fixed logit shift: exp(z-30) never overflows (z<=100.1)

// Scratch (no allocation allowed -> device globals)
__device__ __half g_wn16[Cn * En];   // normalized weight fp16, row-major [C][E]
__device__ float  g_bsum[NPERS];
__device__ int    g_cnt;             // zero-init; reset by last block each launch

// smem byte offsets
#define OFF_A    0                   // half[128][136] = 34816 B (single buffer)
#define OFF_B    34816               // half[128][136] = 34816 B
#define OFF_RED  69632               // float[8]
#define OFF_FLAG 69664               // int
#define SMEM_SZ  69696

__device__ __forceinline__ void hmma16816(float& c0, float& c1, float& c2, float& c3,
                                          uint32_t a0, uint32_t a1, uint32_t a2, uint32_t a3,
                                          uint32_t b0, uint32_t b1) {
    asm volatile(
        "mma.sync.aligned.m16n8k16.row.col.f32.f16.f16.f32 "
        "{%0,%1,%2,%3}, {%4,%5,%6,%7}, {%8,%9}, {%0,%1,%2,%3};"
        : "+f"(c0), "+f"(c1), "+f"(c2), "+f"(c3)
        : "r"(a0), "r"(a1), "r"(a2), "r"(a3), "r"(b0), "r"(b1));
}

// ---------------------------------------------------------------------------
// prep: normalize weight rows -> fp16 row-major global. 16 blocks x 256 thr.
// ---------------------------------------------------------------------------
__global__ void prep_kernel(const float* __restrict__ weight)
{
    const int lane = threadIdx.x & 31;
    const int w    = threadIdx.x >> 5;
    const int row  = blockIdx.x * 8 + w;

    float4 v = reinterpret_cast<const float4*>(weight)[row * 32 + lane];
    float ss = v.x * v.x + v.y * v.y + v.z * v.z + v.w * v.w;
    #pragma unroll
    for (int o = 16; o; o >>= 1) ss += __shfl_xor_sync(0xffffffffu, ss, o);
    float r = 1.0f / fmaxf(sqrtf(ss), 1e-12f);

    __half2 h0 = __floats2half2_rn(v.x * r, v.y * r);
    __half2 h1 = __floats2half2_rn(v.z * r, v.w * r);
    unsigned long long pk;
    asm("mov.b64 %0,{%1,%2};" : "=l"(pk)
        : "r"(*(uint32_t*)&h0), "r"(*(uint32_t*)&h1));
    *reinterpret_cast<unsigned long long*>(
        reinterpret_cast<char*>(g_wn16) + row * 256 + lane * 8) = pk;
}

// NLL from label-EXCLUDED shifted sum se = sum exp(z-30), and label cosine cs.
__device__ __forceinline__ float row_nll(float se, float cs) {
    float sn  = sqrtf(fmaxf(1.0f - cs * cs, 0.0f));
    float phi = (cs > THv) ? (cs * COSM - sn * SINM) : (cs - MMv);
    float zl  = Sv * phi;
    float se2 = se + __expf(zl - SHIFT);
    return (SHIFT + __logf(se2)) - zl;
}

// issue LDGs for 8 rows of predict+target (prefetch into registers)
__device__ __forceinline__ void issue_half(const float* __restrict__ predict,
                                           const float* __restrict__ target,
                                           int tile, int rowLocal, int lane,
                                           float4* Vp, float4* Vt)
{
    const size_t base = ((size_t)tile * TM + rowLocal) * 32 + lane;   // float4 units
    const float4* p4 = (const float4*)predict;
    const float4* t4 = (const float4*)target;
    #pragma unroll
    for (int j = 0; j < 8; j++) {
        Vp[j] = __ldg(p4 + base + (size_t)j * 32);
        Vt[j] = __ldg(t4 + base + (size_t)j * 32);
    }
}

// consume 8 prefetched rows: fp16 convert + STS, butterfly -> row norm^2 + label
__device__ __forceinline__ void consume_half(const float4* Vp, const float4* Vt,
                                             char* sAbuf, int rowLocal, int lane, int g,
                                             float& ssOut, int& lblOut)
{
    float ssq[8], lix[8];
    const float i0 = (float)(lane * 4), i1 = i0 + 1.f, i2 = i0 + 2.f, i3 = i0 + 3.f;
    #pragma unroll
    for (int j = 0; j < 8; j++) {
        float4 v = Vp[j], t = Vt[j];
        __half2 h0 = __floats2half2_rn(v.x, v.y);
        __half2 h1 = __floats2half2_rn(v.z, v.w);
        unsigned long long pk;
        asm("mov.b64 %0,{%1,%2};" : "=l"(pk)
            : "r"(*(uint32_t*)&h0), "r"(*(uint32_t*)&h1));
        *reinterpret_cast<unsigned long long*>(sAbuf + (rowLocal + j) * 272 + lane * 8) = pk;
        ssq[j] = fmaf(v.x, v.x, fmaf(v.y, v.y, fmaf(v.z, v.z, v.w * v.w)));
        lix[j] = fmaf(t.x, i0, fmaf(t.y, i1, fmaf(t.z, i2, t.w * i3)));
    }
    #pragma unroll
    for (int o = 16; o; o >>= 1) {
        #pragma unroll
        for (int i = 0; i < 8; i++) {
            ssq[i] += __shfl_xor_sync(0xffffffffu, ssq[i], o);
            lix[i] += __shfl_xor_sync(0xffffffffu, lix[i], o);
        }
    }
    float ss = 0.f, lf = 0.f;
    #pragma unroll
    for (int i = 0; i < 8; i++) if (i == g) { ss = ssq[i]; lf = lix[i]; }
    ssOut = ss; lblOut = (int)lf;
}

__device__ __forceinline__ void load_afrags(const char* sAbuf, int rb0, int g, int c,
                                            uint32_t* A0, uint32_t* A1,
                                            uint32_t* A2, uint32_t* A3)
{
    const char* a_lo = sAbuf + (rb0 + g) * 272 + c * 4;
    const char* a_hi = a_lo + 8 * 272;
    #pragma unroll
    for (int ks = 0; ks < 8; ks++) {
        A0[ks] = *(const uint32_t*)(a_lo + ks * 32);
        A2[ks] = *(const uint32_t*)(a_lo + ks * 32 + 16);
        A1[ks] = *(const uint32_t*)(a_hi + ks * 32);
        A3[ks] = *(const uint32_t*)(a_hi + ks * 32 + 16);
    }
}

// 8 col-tiles of the mainloop (tstart = 0 or 8, compile-time)
__device__ __forceinline__ void mma_half(int tstart, const char* sB, int g, int c,
    const uint32_t* A0, const uint32_t* A1, const uint32_t* A2, const uint32_t* A3,
    float sI0, float sI1, float invn0, float invn1, int lbl0, int lbl1,
    float& ac00, float& ac01, float& ac10, float& ac11, float& cs0, float& cs1)
{
    #pragma unroll
    for (int t = 0; t < 8; t++) {
        const int tt = tstart + t;
        float c0 = 0.f, c1 = 0.f, c2 = 0.f, c3 = 0.f;
        const char* bb = sB + (8 * tt + g) * 272 + c * 4;
        #pragma unroll
        for (int ks = 0; ks < 8; ks++) {
            uint32_t b0 = *(const uint32_t*)(bb + ks * 32);
            uint32_t b1 = *(const uint32_t*)(bb + ks * 32 + 16);
            hmma16816(c0, c1, c2, c3, A0[ks], A1[ks], A2[ks], A3[ks], b0, b1);
        }
        const int n0 = 8 * tt + 2 * c;
        float e0 = __expf(fmaf(c0, sI0, -SHIFT));
        float e1 = __expf(fmaf(c1, sI0, -SHIFT));
        float e2 = __expf(fmaf(c2, sI1, -SHIFT));
        float e3 = __expf(fmaf(c3, sI1, -SHIFT));
        if (n0     == lbl0) { cs0 = c0 * invn0; e0 = 0.f; }
        if (n0 + 1 == lbl0) { cs0 = c1 * invn0; e1 = 0.f; }
        if (n0     == lbl1) { cs1 = c2 * invn1; e2 = 0.f; }
        if (n0 + 1 == lbl1) { cs1 = c3 * invn1; e3 = 0.f; }
        ac00 += e0; ac01 += e1; ac10 += e2; ac11 += e3;
    }
}

// ---------------------------------------------------------------------------
// main: persistent CTAs, cross-tile register prefetch, warp-private A path
// ---------------------------------------------------------------------------
__global__ void __launch_bounds__(256, 2)
arc_main(const float* __restrict__ predict,
         const float* __restrict__ target,
         float* __restrict__ out)
{
    extern __shared__ char sm[];
    char*  sA   = sm + OFF_A;
    char*  sB   = sm + OFF_B;
    float* red  = (float*)(sm + OFF_RED);
    int*   flag = (int*)(sm + OFF_FLAG);

    const int tid  = threadIdx.x;
    const int lane = tid & 31;
    const int w    = tid >> 5;
    const int g    = lane >> 2;
    const int c    = lane & 3;
    const int rb0  = w * 16;

    // ---- B tile (block-shared, persistent) ----
    {
        const uint4* gw = (const uint4*)g_wn16;
        #pragma unroll
        for (int i = 0; i < 8; i++) {
            int idx = i * 256 + tid;
            *(uint4*)(sB + (idx >> 4) * 272 + (idx & 15) * 16) = gw[idx];
        }
    }
    __syncthreads();

    float4 Vp[8], Vt[8];
    uint32_t A0[8], A1[8], A2[8], A3[8];

    // ---- first tile prologue ----
    int tile = blockIdx.x;
    float ss0, ss1; int lbl0, lbl1;
    issue_half(predict, target, tile, rb0, lane, Vp, Vt);
    consume_half(Vp, Vt, sA, rb0, lane, g, ss0, lbl0);
    issue_half(predict, target, tile, rb0 + 8, lane, Vp, Vt);
    consume_half(Vp, Vt, sA, rb0 + 8, lane, g, ss1, lbl1);
    __syncwarp();
    load_afrags(sA, rb0, g, c, A0, A1, A2, A3);
    float invn0 = rsqrtf(fmaxf(ss0, 1e-24f));
    float invn1 = rsqrtf(fmaxf(ss1, 1e-24f));

    int  next    = tile + NPERS;
    bool hasNext = next < NTILES;
    if (hasNext) issue_half(predict, target, next, rb0, lane, Vp, Vt);

    float nll_acc = 0.f;
    float ns0 = 0.f, ns1 = 0.f; int nl0 = 0, nl1 = 0;

    while (true) {
        const float sI0 = Sv * invn0, sI1 = Sv * invn1;
        float ac00 = 0.f, ac01 = 0.f, ac10 = 0.f, ac11 = 0.f;
        float cs0 = -2.0f, cs1 = -2.0f;

        mma_half(0, sB, g, c, A0, A1, A2, A3, sI0, sI1, invn0, invn1, lbl0, lbl1,
                 ac00, ac01, ac10, ac11, cs0, cs1);

        if (hasNext) {
            // A regs hold tile i; smem A rows are dead -> overwrite in place
            consume_half(Vp, Vt, sA, rb0, lane, g, ns0, nl0);
            issue_half(predict, target, next, rb0 + 8, lane, Vp, Vt);
        }

        mma_half(8, sB, g, c, A0, A1, A2, A3, sI0, sI1, invn0, invn1, lbl0, lbl1,
                 ac00, ac01, ac10, ac11, cs0, cs1);

        // ---- tile epilogue ----
        float se0 = ac00 + ac01, se1 = ac10 + ac11;
        se0 += __shfl_xor_sync(0xffffffffu, se0, 1);
        se0 += __shfl_xor_sync(0xffffffffu, se0, 2);
        se1 += __shfl_xor_sync(0xffffffffu, se1, 1);
        se1 += __shfl_xor_sync(0xffffffffu, se1, 2);
        cs0 = fmaxf(cs0, __shfl_xor_sync(0xffffffffu, cs0, 1));
        cs0 = fmaxf(cs0, __shfl_xor_sync(0xffffffffu, cs0, 2));
        cs1 = fmaxf(cs1, __shfl_xor_sync(0xffffffffu, cs1, 1));
        cs1 = fmaxf(cs1, __shfl_xor_sync(0xffffffffu, cs1, 2));
        if (c == 0) nll_acc += row_nll(se0, cs0) + row_nll(se1, cs1);

        if (!hasNext) break;

        consume_half(Vp, Vt, sA, rb0 + 8, lane, g, ns1, nl1);
        __syncwarp();
        load_afrags(sA, rb0, g, c, A0, A1, A2, A3);
        invn0 = rsqrtf(fmaxf(ns0, 1e-24f));
        invn1 = rsqrtf(fmaxf(ns1, 1e-24f));
        lbl0 = nl0; lbl1 = nl1;

        tile = next; next += NPERS; hasNext = next < NTILES;
        if (hasNext) issue_half(predict, target, next, rb0, lane, Vp, Vt);
    }

    // ---- warp & block reduction of accumulated NLL ----
    float nll = nll_acc;
    #pragma unroll
    for (int o = 16; o; o >>= 1) nll += __shfl_xor_sync(0xffffffffu, nll, o);
    if (lane == 0) red[w] = nll;
    __syncthreads();

    if (tid == 0) {
        float t = 0.0f;
        #pragma unroll
        for (int i = 0; i < 8; i++) t += red[i];
        g_bsum[blockIdx.x] = t;
        __threadfence();
        int cdone = atomicAdd(&g_cnt, 1);
        *flag = (cdone == NPERS - 1) ? 1 : 0;
    }
    __syncthreads();

    // last CTA: deterministic final reduction -> mean
    if (*flag) {
        __threadfence();
        float t = g_bsum[tid];
        if (tid + 256 < NPERS) t += g_bsum[tid + 256];
        float* fr = (float*)sA;   // reuse smem
        fr[tid] = t;
        __syncthreads();
        #pragma unroll
        for (int st = 128; st; st >>= 1) {
            if (tid < st) fr[tid] += fr[tid + st];
            __syncthreads();
        }
        if (tid == 0) {
            out[0] = fr[0] / (float)Bn;
            g_cnt  = 0;
        }
    }
}

// ---------------------------------------------------------------------------
extern "C" void kernel_launch(void* const* d_in, const int* in_sizes, int n_in,
                              void* d_out, int out_size)
{
    (void)in_sizes; (void)n_in; (void)out_size;
    const float* predict = (const float*)d_in[0];
    const float* target  = (const float*)d_in[1];
    const float* weight  = (const float*)d_in[2];

    cudaFuncSetAttribute(arc_main, cudaFuncAttributeMaxDynamicSharedMemorySize, SMEM_SZ);

    prep_kernel<<<16, 256>>>(weight);
    arc_main<<<NPERS, 256, SMEM_SZ>>>(predict, target, (float*)d_out);
}

// round 9
// speedup vs baseline: 1.4354x; 1.0400x over previous
#include <cuda_runtime.h>
#include <cuda_fp16.h>
#include <cstdint>

// Problem constants
#define Bn 131072
#define Cn 128
#define En 128
#define TM 128              // samples per tile
#define NTILES (Bn / TM)    // 1024
#define NPERS 296           // persistent CTAs (2 per SM on 148 SMs)

// ArcFace constants (m = 1.0, s = 100)
#define COSM 0.5403023058681398f
#define SINM 0.8414709848078965f
#define THv  (-0.5403023058681398f)
#define MMv  0.8414709848078965f
#define Sv   100.0f
#define SHIFT 30.0f         // fixed logit shift: exp(z-30) never overflows (z<=100.1)

// Scratch (no allocation allowed -> device globals)
__device__ uint32_t g_wfrag[8192];   // 32KB: normalized weight fp16 in HMMA fragment order
__device__ float    g_bsum[NPERS];
__device__ int      g_cnt;           // zero-init; reset by last block each launch

// smem layout
//   A: half[128][136] rows stride 272B              -> 34816 B
//   B: fragment order, 512 lane-rows x 80B stride   -> 40960 B (64B data + 16B pad)
#define OFF_A    0
#define OFF_B    34816
#define OFF_RED  75776               // float[8]
#define OFF_FLAG 75808               // int
#define SMEM_SZ  75840

__device__ __forceinline__ void hmma16816(float& c0, float& c1, float& c2, float& c3,
                                          uint32_t a0, uint32_t a1, uint32_t a2, uint32_t a3,
                                          uint32_t b0, uint32_t b1) {
    asm volatile(
        "mma.sync.aligned.m16n8k16.row.col.f32.f16.f16.f32 "
        "{%0,%1,%2,%3}, {%4,%5,%6,%7}, {%8,%9}, {%0,%1,%2,%3};"
        : "+f"(c0), "+f"(c1), "+f"(c2), "+f"(c3)
        : "r"(a0), "r"(a1), "r"(a2), "r"(a3), "r"(b0), "r"(b1));
}

// ---------------------------------------------------------------------------
// prep: normalize weight rows -> fragment-ordered fp16 global.
// Fragment order: word for (tile t, lane 4g+c, k-step ks, b) at
//   idx = (t*32 + 4g + c)*16 + 2*ks + b,  covering k = 16ks + 8b + 2c (+1).
// A lane holding halves m=2*lane, 2*lane+1 (m = k/2 = 8ks+4b+c) scatters them.
// ---------------------------------------------------------------------------
__global__ void prep_kernel(const float* __restrict__ weight)
{
    const int lane = threadIdx.x & 31;
    const int w    = threadIdx.x >> 5;
    const int row  = blockIdx.x * 8 + w;          // class n
    const int g    = row & 7;
    const int t    = row >> 3;

    float4 v = reinterpret_cast<const float4*>(weight)[row * 32 + lane];
    float ss = v.x * v.x + v.y * v.y + v.z * v.z + v.w * v.w;
    #pragma unroll
    for (int o = 16; o; o >>= 1) ss += __shfl_xor_sync(0xffffffffu, ss, o);
    float r = 1.0f / fmaxf(sqrtf(ss), 1e-12f);

    __half2 h0 = __floats2half2_rn(v.x * r, v.y * r);   // halves m = 2*lane
    __half2 h1 = __floats2half2_rn(v.z * r, v.w * r);   // halves m = 2*lane+1

    #pragma unroll
    for (int j = 0; j < 2; j++) {
        const int m  = 2 * lane + j;
        const int c  = m & 3, b = (m >> 2) & 1, ks = m >> 3;
        const int di = (t * 32 + g * 4 + c) * 16 + 2 * ks + b;
        g_wfrag[di] = (j == 0) ? *(uint32_t*)&h0 : *(uint32_t*)&h1;
    }
}

// NLL from label-EXCLUDED shifted sum se = sum exp(z-30), and label cosine cs.
__device__ __forceinline__ float row_nll(float se, float cs) {
    float sn  = sqrtf(fmaxf(1.0f - cs * cs, 0.0f));
    float phi = (cs > THv) ? (cs * COSM - sn * SINM) : (cs - MMv);
    float zl  = Sv * phi;
    float se2 = se + __expf(zl - SHIFT);
    return (SHIFT + __logf(se2)) - zl;
}

// issue LDGs for 8 rows of predict+target (prefetch into registers)
__device__ __forceinline__ void issue_half(const float* __restrict__ predict,
                                           const float* __restrict__ target,
                                           int tile, int rowLocal, int lane,
                                           float4* Vp, float4* Vt)
{
    const size_t base = ((size_t)tile * TM + rowLocal) * 32 + lane;   // float4 units
    const float4* p4 = (const float4*)predict;
    const float4* t4 = (const float4*)target;
    #pragma unroll
    for (int j = 0; j < 8; j++) {
        Vp[j] = __ldg(p4 + base + (size_t)j * 32);
        Vt[j] = __ldg(t4 + base + (size_t)j * 32);
    }
}

// consume 8 prefetched rows: fp16 convert + STS, butterfly -> row norm^2 + label
__device__ __forceinline__ void consume_half(const float4* Vp, const float4* Vt,
                                             char* sAbuf, int rowLocal, int lane, int g,
                                             float& ssOut, int& lblOut)
{
    float ssq[8], lix[8];
    const float i0 = (float)(lane * 4), i1 = i0 + 1.f, i2 = i0 + 2.f, i3 = i0 + 3.f;
    #pragma unroll
    for (int j = 0; j < 8; j++) {
        float4 v = Vp[j], t = Vt[j];
        __half2 h0 = __floats2half2_rn(v.x, v.y);
        __half2 h1 = __floats2half2_rn(v.z, v.w);
        unsigned long long pk;
        asm("mov.b64 %0,{%1,%2};" : "=l"(pk)
            : "r"(*(uint32_t*)&h0), "r"(*(uint32_t*)&h1));
        *reinterpret_cast<unsigned long long*>(sAbuf + (rowLocal + j) * 272 + lane * 8) = pk;
        ssq[j] = fmaf(v.x, v.x, fmaf(v.y, v.y, fmaf(v.z, v.z, v.w * v.w)));
        lix[j] = fmaf(t.x, i0, fmaf(t.y, i1, fmaf(t.z, i2, t.w * i3)));
    }
    #pragma unroll
    for (int o = 16; o; o >>= 1) {
        #pragma unroll
        for (int i = 0; i < 8; i++) {
            ssq[i] += __shfl_xor_sync(0xffffffffu, ssq[i], o);
            lix[i] += __shfl_xor_sync(0xffffffffu, lix[i], o);
        }
    }
    float ss = 0.f, lf = 0.f;
    #pragma unroll
    for (int i = 0; i < 8; i++) if (i == g) { ss = ssq[i]; lf = lix[i]; }
    ssOut = ss; lblOut = (int)lf;
}

__device__ __forceinline__ void load_afrags(const char* sAbuf, int rb0, int g, int c,
                                            uint32_t* A0, uint32_t* A1,
                                            uint32_t* A2, uint32_t* A3)
{
    const char* a_lo = sAbuf + (rb0 + g) * 272 + c * 4;
    const char* a_hi = a_lo + 8 * 272;
    #pragma unroll
    for (int ks = 0; ks < 8; ks++) {
        A0[ks] = *(const uint32_t*)(a_lo + ks * 32);
        A2[ks] = *(const uint32_t*)(a_lo + ks * 32 + 16);
        A1[ks] = *(const uint32_t*)(a_hi + ks * 32);
        A3[ks] = *(const uint32_t*)(a_hi + ks * 32 + 16);
    }
}

// 8 col-tiles of the mainloop; B via LDS.128 fragment loads (4 per tile)
__device__ __forceinline__ void mma_half(int tstart, const char* sB, int lane, int c,
    const uint32_t* A0, const uint32_t* A1, const uint32_t* A2, const uint32_t* A3,
    float sI0, float sI1, float invn0, float invn1, int lbl0, int lbl1,
    float& ac00, float& ac01, float& ac10, float& ac11, float& cs0, float& cs1)
{
    #pragma unroll
    for (int t = 0; t < 8; t++) {
        const int tt = tstart + t;
        float c0 = 0.f, c1 = 0.f, c2 = 0.f, c3 = 0.f;
        const char* bb = sB + (tt * 32 + lane) * 80;
        #pragma unroll
        for (int q = 0; q < 4; q++) {
            const uint4 bv = *(const uint4*)(bb + q * 16);
            hmma16816(c0, c1, c2, c3,
                      A0[2*q], A1[2*q], A2[2*q], A3[2*q], bv.x, bv.y);
            hmma16816(c0, c1, c2, c3,
                      A0[2*q+1], A1[2*q+1], A2[2*q+1], A3[2*q+1], bv.z, bv.w);
        }
        const int n0 = 8 * tt + 2 * c;
        float e0 = __expf(fmaf(c0, sI0, -SHIFT));
        float e1 = __expf(fmaf(c1, sI0, -SHIFT));
        float e2 = __expf(fmaf(c2, sI1, -SHIFT));
        float e3 = __expf(fmaf(c3, sI1, -SHIFT));
        if (n0     == lbl0) { cs0 = c0 * invn0; e0 = 0.f; }
        if (n0 + 1 == lbl0) { cs0 = c1 * invn0; e1 = 0.f; }
        if (n0     == lbl1) { cs1 = c2 * invn1; e2 = 0.f; }
        if (n0 + 1 == lbl1) { cs1 = c3 * invn1; e3 = 0.f; }
        ac00 += e0; ac01 += e1; ac10 += e2; ac11 += e3;
    }
}

// ---------------------------------------------------------------------------
// main: persistent CTAs, cross-tile register prefetch, vectorized B fragments
// ---------------------------------------------------------------------------
__global__ void __launch_bounds__(256, 2)
arc_main(const float* __restrict__ predict,
         const float* __restrict__ target,
         float* __restrict__ out)
{
    extern __shared__ char sm[];
    char*  sA   = sm + OFF_A;
    char*  sB   = sm + OFF_B;
    float* red  = (float*)(sm + OFF_RED);
    int*   flag = (int*)(sm + OFF_FLAG);

    const int tid  = threadIdx.x;
    const int lane = tid & 31;
    const int w    = tid >> 5;
    const int g    = lane >> 2;
    const int c    = lane & 3;
    const int rb0  = w * 16;

    // ---- B tile: fragment-ordered copy, 80B lane stride (conflict-free) ----
    {
        const uint4* gw = (const uint4*)g_wfrag;    // 2048 uint4
        #pragma unroll
        for (int i = 0; i < 8; i++) {
            int idx = i * 256 + tid;                // uint4 index
            *(uint4*)(sB + (idx >> 2) * 80 + (idx & 3) * 16) = gw[idx];
        }
    }
    __syncthreads();

    float4 Vp[8], Vt[8];
    uint32_t A0[8], A1[8], A2[8], A3[8];

    // ---- first tile prologue ----
    int tile = blockIdx.x;
    float ss0, ss1; int lbl0, lbl1;
    issue_half(predict, target, tile, rb0, lane, Vp, Vt);
    consume_half(Vp, Vt, sA, rb0, lane, g, ss0, lbl0);
    issue_half(predict, target, tile, rb0 + 8, lane, Vp, Vt);
    consume_half(Vp, Vt, sA, rb0 + 8, lane, g, ss1, lbl1);
    __syncwarp();
    load_afrags(sA, rb0, g, c, A0, A1, A2, A3);
    float invn0 = rsqrtf(fmaxf(ss0, 1e-24f));
    float invn1 = rsqrtf(fmaxf(ss1, 1e-24f));

    int  next    = tile + NPERS;
    bool hasNext = next < NTILES;
    if (hasNext) issue_half(predict, target, next, rb0, lane, Vp, Vt);

    float nll_acc = 0.f;
    float ns0 = 0.f, ns1 = 0.f; int nl0 = 0, nl1 = 0;

    while (true) {
        const float sI0 = Sv * invn0, sI1 = Sv * invn1;
        float ac00 = 0.f, ac01 = 0.f, ac10 = 0.f, ac11 = 0.f;
        float cs0 = -2.0f, cs1 = -2.0f;

        mma_half(0, sB, lane, c, A0, A1, A2, A3, sI0, sI1, invn0, invn1, lbl0, lbl1,
                 ac00, ac01, ac10, ac11, cs0, cs1);

        if (hasNext) {
            // A regs hold tile i; smem A rows are dead -> overwrite in place
            consume_half(Vp, Vt, sA, rb0, lane, g, ns0, nl0);
            issue_half(predict, target, next, rb0 + 8, lane, Vp, Vt);
        }

        mma_half(8, sB, lane, c, A0, A1, A2, A3, sI0, sI1, invn0, invn1, lbl0, lbl1,
                 ac00, ac01, ac10, ac11, cs0, cs1);

        // ---- tile epilogue ----
        float se0 = ac00 + ac01, se1 = ac10 + ac11;
        se0 += __shfl_xor_sync(0xffffffffu, se0, 1);
        se0 += __shfl_xor_sync(0xffffffffu, se0, 2);
        se1 += __shfl_xor_sync(0xffffffffu, se1, 1);
        se1 += __shfl_xor_sync(0xffffffffu, se1, 2);
        cs0 = fmaxf(cs0, __shfl_xor_sync(0xffffffffu, cs0, 1));
        cs0 = fmaxf(cs0, __shfl_xor_sync(0xffffffffu, cs0, 2));
        cs1 = fmaxf(cs1, __shfl_xor_sync(0xffffffffu, cs1, 1));
        cs1 = fmaxf(cs1, __shfl_xor_sync(0xffffffffu, cs1, 2));
        if (c == 0) nll_acc += row_nll(se0, cs0) + row_nll(se1, cs1);

        if (!hasNext) break;

        consume_half(Vp, Vt, sA, rb0 + 8, lane, g, ns1, nl1);
        __syncwarp();
        load_afrags(sA, rb0, g, c, A0, A1, A2, A3);
        invn0 = rsqrtf(fmaxf(ns0, 1e-24f));
        invn1 = rsqrtf(fmaxf(ns1, 1e-24f));
        lbl0 = nl0; lbl1 = nl1;

        tile = next; next += NPERS; hasNext = next < NTILES;
        if (hasNext) issue_half(predict, target, next, rb0, lane, Vp, Vt);
    }

    // ---- warp & block reduction of accumulated NLL ----
    float nll = nll_acc;
    #pragma unroll
    for (int o = 16; o; o >>= 1) nll += __shfl_xor_sync(0xffffffffu, nll, o);
    if (lane == 0) red[w] = nll;
    __syncthreads();

    if (tid == 0) {
        float t = 0.0f;
        #pragma unroll
        for (int i = 0; i < 8; i++) t += red[i];
        g_bsum[blockIdx.x] = t;
        __threadfence();
        int cdone = atomicAdd(&g_cnt, 1);
        *flag = (cdone == NPERS - 1) ? 1 : 0;
    }
    __syncthreads();

    // last CTA: deterministic final reduction -> mean
    if (*flag) {
        __threadfence();
        float t = g_bsum[tid];
        if (tid + 256 < NPERS) t += g_bsum[tid + 256];
        float* fr = (float*)sA;   // reuse smem
        fr[tid] = t;
        __syncthreads();
        #pragma unroll
        for (int st = 128; st; st >>= 1) {
            if (tid < st) fr[tid] += fr[tid + st];
            __syncthreads();
        }
        if (tid == 0) {
            out[0] = fr[0] / (float)Bn;
            g_cnt  = 0;
        }
    }
}

// ---------------------------------------------------------------------------
extern "C" void kernel_launch(void* const* d_in, const int* in_sizes, int n_in,
                              void* d_out, int out_size)
{
    (void)in_sizes; (void)n_in; (void)out_size;
    const float* predict = (const float*)d_in[0];
    const float* target  = (const float*)d_in[1];
    const float* weight  = (const float*)d_in[2];

    cudaFuncSetAttribute(arc_main, cudaFuncAttributeMaxDynamicSharedMemorySize, SMEM_SZ);

    prep_kernel<<<16, 256>>>(weight);
    arc_main<<<NPERS, 256, SMEM_SZ>>>(predict, target, (float*)d_out);
}